// round 1
// baseline (speedup 1.0000x reference)
#include <cuda_runtime.h>
#include <math.h>

#define BATCH 8
#define LQ 2048
#define LK 2048
#define DIM 640

#define INV_TEMP (1.0f / 13.0f)

// Scratch for row sums of squares (allocation-free rule: __device__ globals)
__device__ float g_qq[BATCH * LQ];
__device__ float g_kk[BATCH * LK];

// ---------------------------------------------------------------------------
// Pass 1: row sum-of-squares for q and k
// grid = 2*BATCH*LQ blocks of 128 threads; first half -> qq, second -> kk
// ---------------------------------------------------------------------------
__global__ void sumsq_kernel(const float* __restrict__ q,
                             const float* __restrict__ k) {
    int row = blockIdx.x;
    const float* p;
    float* o;
    if (row < BATCH * LQ) {
        p = q + (size_t)row * DIM;
        o = &g_qq[row];
    } else {
        int r = row - BATCH * LQ;
        p = k + (size_t)r * DIM;
        o = &g_kk[r];
    }
    float s = 0.f;
    for (int i = threadIdx.x; i < DIM; i += 128) {
        float v = p[i];
        s = fmaf(v, v, s);
    }
#pragma unroll
    for (int off = 16; off > 0; off >>= 1)
        s += __shfl_down_sync(0xffffffffu, s, off);
    __shared__ float ws[4];
    if ((threadIdx.x & 31) == 0) ws[threadIdx.x >> 5] = s;
    __syncthreads();
    if (threadIdx.x == 0) *o = ws[0] + ws[1] + ws[2] + ws[3];
}

// ---------------------------------------------------------------------------
// Pass 2: S = Q @ K^T with epilogue logits = (2*s - qq - kk) / 13
// 128x128x16 tiles, 256 threads, 8x8 per-thread microkernel, double buffered.
// Both operands are K-major (D contiguous). Writes into log_attn region.
// ---------------------------------------------------------------------------
#define BM 128
#define BN 128
#define BK 16

__global__ __launch_bounds__(256, 2)
void gemm_qk_kernel(const float* __restrict__ Q, const float* __restrict__ K,
                    float* __restrict__ logits) {
    int b = blockIdx.z;
    int m0 = blockIdx.y * BM;
    int n0 = blockIdx.x * BN;
    const float* Ab = Q + (size_t)b * LQ * DIM;
    const float* Bb = K + (size_t)b * LK * DIM;
    float* Cb = logits + (size_t)b * LQ * LK;

    __shared__ float As[2][BK][BM];
    __shared__ float Bs[2][BK][BN];

    int t = threadIdx.x;
    int tx = t & 15;        // 0..15 -> 8 cols each
    int ty = t >> 4;        // 0..15 -> 8 rows each

    // tile-load mapping: 128 rows x 4 float4 (16 k) per tile
    int r0 = t >> 2;        // 0..63
    int c0 = t & 3;         // float4 column (k/4)

    float acc[8][8];
#pragma unroll
    for (int i = 0; i < 8; i++)
#pragma unroll
        for (int j = 0; j < 8; j++) acc[i][j] = 0.f;

    // prologue: load k-tile 0 into buffer 0
    {
        const float* ap = Ab + (size_t)(m0 + r0) * DIM + c0 * 4;
        float4 a0 = *(const float4*)ap;
        float4 a1 = *(const float4*)(ap + (size_t)64 * DIM);
        const float* bp = Bb + (size_t)(n0 + r0) * DIM + c0 * 4;
        float4 b0 = *(const float4*)bp;
        float4 b1 = *(const float4*)(bp + (size_t)64 * DIM);
        As[0][c0 * 4 + 0][r0] = a0.x; As[0][c0 * 4 + 1][r0] = a0.y;
        As[0][c0 * 4 + 2][r0] = a0.z; As[0][c0 * 4 + 3][r0] = a0.w;
        As[0][c0 * 4 + 0][r0 + 64] = a1.x; As[0][c0 * 4 + 1][r0 + 64] = a1.y;
        As[0][c0 * 4 + 2][r0 + 64] = a1.z; As[0][c0 * 4 + 3][r0 + 64] = a1.w;
        Bs[0][c0 * 4 + 0][r0] = b0.x; Bs[0][c0 * 4 + 1][r0] = b0.y;
        Bs[0][c0 * 4 + 2][r0] = b0.z; Bs[0][c0 * 4 + 3][r0] = b0.w;
        Bs[0][c0 * 4 + 0][r0 + 64] = b1.x; Bs[0][c0 * 4 + 1][r0 + 64] = b1.y;
        Bs[0][c0 * 4 + 2][r0 + 64] = b1.z; Bs[0][c0 * 4 + 3][r0 + 64] = b1.w;
    }
    __syncthreads();

    const int KT = DIM / BK;   // 40
    for (int kt = 0; kt < KT; kt++) {
        int cur = kt & 1, nxt = cur ^ 1;
        float4 na0, na1, nb0, nb1;
        bool more = (kt + 1 < KT);
        if (more) {
            const float* ap = Ab + (size_t)(m0 + r0) * DIM + (kt + 1) * BK + c0 * 4;
            na0 = *(const float4*)ap;
            na1 = *(const float4*)(ap + (size_t)64 * DIM);
            const float* bp = Bb + (size_t)(n0 + r0) * DIM + (kt + 1) * BK + c0 * 4;
            nb0 = *(const float4*)bp;
            nb1 = *(const float4*)(bp + (size_t)64 * DIM);
        }
#pragma unroll
        for (int kk = 0; kk < BK; kk++) {
            float a[8], bb[8];
            *(float4*)&a[0] = *(const float4*)&As[cur][kk][ty * 8];
            *(float4*)&a[4] = *(const float4*)&As[cur][kk][ty * 8 + 4];
            *(float4*)&bb[0] = *(const float4*)&Bs[cur][kk][tx * 8];
            *(float4*)&bb[4] = *(const float4*)&Bs[cur][kk][tx * 8 + 4];
#pragma unroll
            for (int i = 0; i < 8; i++)
#pragma unroll
                for (int j = 0; j < 8; j++)
                    acc[i][j] = fmaf(a[i], bb[j], acc[i][j]);
        }
        if (more) {
            As[nxt][c0 * 4 + 0][r0] = na0.x; As[nxt][c0 * 4 + 1][r0] = na0.y;
            As[nxt][c0 * 4 + 2][r0] = na0.z; As[nxt][c0 * 4 + 3][r0] = na0.w;
            As[nxt][c0 * 4 + 0][r0 + 64] = na1.x; As[nxt][c0 * 4 + 1][r0 + 64] = na1.y;
            As[nxt][c0 * 4 + 2][r0 + 64] = na1.z; As[nxt][c0 * 4 + 3][r0 + 64] = na1.w;
            Bs[nxt][c0 * 4 + 0][r0] = nb0.x; Bs[nxt][c0 * 4 + 1][r0] = nb0.y;
            Bs[nxt][c0 * 4 + 2][r0] = nb0.z; Bs[nxt][c0 * 4 + 3][r0] = nb0.w;
            Bs[nxt][c0 * 4 + 0][r0 + 64] = nb1.x; Bs[nxt][c0 * 4 + 1][r0 + 64] = nb1.y;
            Bs[nxt][c0 * 4 + 2][r0 + 64] = nb1.z; Bs[nxt][c0 * 4 + 3][r0 + 64] = nb1.w;
            __syncthreads();
        }
    }

    // epilogue: logits = (2*s - qq - kk) / 13
    float qrow[8], kcol[8];
#pragma unroll
    for (int i = 0; i < 8; i++) qrow[i] = g_qq[b * LQ + m0 + ty * 8 + i];
#pragma unroll
    for (int j = 0; j < 8; j++) kcol[j] = g_kk[b * LK + n0 + tx * 8 + j];

#pragma unroll
    for (int i = 0; i < 8; i++) {
        float4 v0, v1;
        float* vp0 = &v0.x;
        float* vp1 = &v1.x;
#pragma unroll
        for (int j = 0; j < 4; j++)
            vp0[j] = (2.f * acc[i][j] - qrow[i] - kcol[j]) * INV_TEMP;
#pragma unroll
        for (int j = 0; j < 4; j++)
            vp1[j] = (2.f * acc[i][4 + j] - qrow[i] - kcol[4 + j]) * INV_TEMP;
        float* cp = Cb + (size_t)(m0 + ty * 8 + i) * LK + n0 + tx * 8;
        *(float4*)cp = v0;
        *(float4*)(cp + 4) = v1;
    }
}

// ---------------------------------------------------------------------------
// Pass 3: row softmax. Reads logits (in log_attn region), rewrites log_attn
// in place and writes attn = exp(log_attn). One block (256 thr) per row.
// ---------------------------------------------------------------------------
__global__ __launch_bounds__(256)
void softmax_kernel(float* __restrict__ logattn, float* __restrict__ attn) {
    size_t row = blockIdx.x;
    float* lp = logattn + row * LK;
    float* ap = attn + row * LK;
    int t = threadIdx.x;

    float x[8];
#pragma unroll
    for (int j = 0; j < 8; j++) x[j] = lp[t + j * 256];

    float m = x[0];
#pragma unroll
    for (int j = 1; j < 8; j++) m = fmaxf(m, x[j]);
#pragma unroll
    for (int off = 16; off > 0; off >>= 1)
        m = fmaxf(m, __shfl_xor_sync(0xffffffffu, m, off));
    __shared__ float red[8];
    __shared__ float bval;
    if ((t & 31) == 0) red[t >> 5] = m;
    __syncthreads();
    if (t == 0) {
        float mm = red[0];
#pragma unroll
        for (int w = 1; w < 8; w++) mm = fmaxf(mm, red[w]);
        bval = mm;
    }
    __syncthreads();
    m = bval;

    float s = 0.f;
#pragma unroll
    for (int j = 0; j < 8; j++) s += expf(x[j] - m);
#pragma unroll
    for (int off = 16; off > 0; off >>= 1)
        s += __shfl_xor_sync(0xffffffffu, s, off);
    __syncthreads();
    if ((t & 31) == 0) red[t >> 5] = s;
    __syncthreads();
    if (t == 0) {
        float ss = 0.f;
#pragma unroll
        for (int w = 0; w < 8; w++) ss += red[w];
        bval = m + logf(ss);
    }
    __syncthreads();
    float lse = bval;

#pragma unroll
    for (int j = 0; j < 8; j++) {
        float la = x[j] - lse;
        lp[t + j * 256] = la;
        ap[t + j * 256] = expf(la);
    }
}

// ---------------------------------------------------------------------------
// Pass 4: output = attn @ V.  M=2048, N=640, K=2048.
// A (attn) is K-major; B (v) is N-major (direct copy, no transpose).
// ---------------------------------------------------------------------------
__global__ __launch_bounds__(256, 2)
void gemm_av_kernel(const float* __restrict__ A, const float* __restrict__ V,
                    float* __restrict__ O) {
    int b = blockIdx.z;
    int m0 = blockIdx.y * BM;
    int n0 = blockIdx.x * BN;
    const float* Ab = A + (size_t)b * LQ * LK;
    const float* Bb = V + (size_t)b * LK * DIM;
    float* Cb = O + (size_t)b * LQ * DIM;

    __shared__ float As[2][BK][BM];
    __shared__ float Bs[2][BK][BN];

    int t = threadIdx.x;
    int tx = t & 15;
    int ty = t >> 4;

    // A tile mapping (transpose store): 128 rows x 4 f4 cols
    int ar = t >> 2;
    int ac = t & 3;
    // B tile mapping (direct): 16 rows x 32 f4 cols
    int br = t >> 5;       // 0..7 (and +8 for second half)
    int bc = t & 31;       // f4 column

    float acc[8][8];
#pragma unroll
    for (int i = 0; i < 8; i++)
#pragma unroll
        for (int j = 0; j < 8; j++) acc[i][j] = 0.f;

    {
        const float* apt = Ab + (size_t)(m0 + ar) * LK + ac * 4;
        float4 a0 = *(const float4*)apt;
        float4 a1 = *(const float4*)(apt + (size_t)64 * LK);
        const float* bpt = Bb + (size_t)br * DIM + n0 + bc * 4;
        float4 b0 = *(const float4*)bpt;
        float4 b1 = *(const float4*)(bpt + (size_t)8 * DIM);
        As[0][ac * 4 + 0][ar] = a0.x; As[0][ac * 4 + 1][ar] = a0.y;
        As[0][ac * 4 + 2][ar] = a0.z; As[0][ac * 4 + 3][ar] = a0.w;
        As[0][ac * 4 + 0][ar + 64] = a1.x; As[0][ac * 4 + 1][ar + 64] = a1.y;
        As[0][ac * 4 + 2][ar + 64] = a1.z; As[0][ac * 4 + 3][ar + 64] = a1.w;
        *(float4*)&Bs[0][br][bc * 4] = b0;
        *(float4*)&Bs[0][br + 8][bc * 4] = b1;
    }
    __syncthreads();

    const int KT = LK / BK;   // 128
    for (int kt = 0; kt < KT; kt++) {
        int cur = kt & 1, nxt = cur ^ 1;
        float4 na0, na1, nb0, nb1;
        bool more = (kt + 1 < KT);
        if (more) {
            const float* apt = Ab + (size_t)(m0 + ar) * LK + (kt + 1) * BK + ac * 4;
            na0 = *(const float4*)apt;
            na1 = *(const float4*)(apt + (size_t)64 * LK);
            const float* bpt = Bb + (size_t)((kt + 1) * BK + br) * DIM + n0 + bc * 4;
            nb0 = *(const float4*)bpt;
            nb1 = *(const float4*)(bpt + (size_t)8 * DIM);
        }
#pragma unroll
        for (int kk = 0; kk < BK; kk++) {
            float a[8], bb[8];
            *(float4*)&a[0] = *(const float4*)&As[cur][kk][ty * 8];
            *(float4*)&a[4] = *(const float4*)&As[cur][kk][ty * 8 + 4];
            *(float4*)&bb[0] = *(const float4*)&Bs[cur][kk][tx * 8];
            *(float4*)&bb[4] = *(const float4*)&Bs[cur][kk][tx * 8 + 4];
#pragma unroll
            for (int i = 0; i < 8; i++)
#pragma unroll
                for (int j = 0; j < 8; j++)
                    acc[i][j] = fmaf(a[i], bb[j], acc[i][j]);
        }
        if (more) {
            As[nxt][ac * 4 + 0][ar] = na0.x; As[nxt][ac * 4 + 1][ar] = na0.y;
            As[nxt][ac * 4 + 2][ar] = na0.z; As[nxt][ac * 4 + 3][ar] = na0.w;
            As[nxt][ac * 4 + 0][ar + 64] = na1.x; As[nxt][ac * 4 + 1][ar + 64] = na1.y;
            As[nxt][ac * 4 + 2][ar + 64] = na1.z; As[nxt][ac * 4 + 3][ar + 64] = na1.w;
            *(float4*)&Bs[nxt][br][bc * 4] = nb0;
            *(float4*)&Bs[nxt][br + 8][bc * 4] = nb1;
            __syncthreads();
        }
    }

#pragma unroll
    for (int i = 0; i < 8; i++) {
        float* cp = Cb + (size_t)(m0 + ty * 8 + i) * DIM + n0 + tx * 8;
        *(float4*)cp = *(float4*)&acc[i][0];
        *(float4*)(cp + 4) = *(float4*)&acc[i][4];
    }
}

// ---------------------------------------------------------------------------
extern "C" void kernel_launch(void* const* d_in, const int* in_sizes, int n_in,
                              void* d_out, int out_size) {
    const float* q = (const float*)d_in[0];
    const float* k = (const float*)d_in[1];
    const float* v = (const float*)d_in[2];

    float* out = (float*)d_out;                                   // (B, Lq, D)
    float* attn = out + (size_t)BATCH * LQ * DIM;                 // (B, Lq, Lk)
    float* logattn = attn + (size_t)BATCH * LQ * LK;              // (B, Lq, Lk)

    // Pass 1: row sums of squares
    sumsq_kernel<<<2 * BATCH * LQ, 128>>>(q, k);

    // Pass 2: logits into log_attn region
    dim3 g1(LK / BN, LQ / BM, BATCH);
    gemm_qk_kernel<<<g1, 256>>>(q, k, logattn);

    // Pass 3: softmax (in-place log_attn, writes attn)
    softmax_kernel<<<BATCH * LQ, 256>>>(logattn, attn);

    // Pass 4: output = attn @ V
    dim3 g2(DIM / BN, LQ / BM, BATCH);
    gemm_av_kernel<<<g2, 256>>>(attn, v, out);
}

// round 2
// speedup vs baseline: 1.0007x; 1.0007x over previous
#include <cuda_runtime.h>
#include <math.h>

#define BATCH 8
#define LQ 2048
#define LK 2048
#define DIM 640

#define INV_TEMP (1.0f / 13.0f)

// Scratch for row sums of squares (allocation-free rule: __device__ globals)
__device__ float g_qq[BATCH * LQ];
__device__ float g_kk[BATCH * LK];

// ---------------------------------------------------------------------------
// Pass 1: row sum-of-squares for q and k
// grid = 2*BATCH*LQ blocks of 128 threads; first half -> qq, second -> kk
// ---------------------------------------------------------------------------
__global__ void sumsq_kernel(const float* __restrict__ q,
                             const float* __restrict__ k) {
    int row = blockIdx.x;
    const float* p;
    float* o;
    if (row < BATCH * LQ) {
        p = q + (size_t)row * DIM;
        o = &g_qq[row];
    } else {
        int r = row - BATCH * LQ;
        p = k + (size_t)r * DIM;
        o = &g_kk[r];
    }
    float s = 0.f;
    for (int i = threadIdx.x; i < DIM; i += 128) {
        float v = p[i];
        s = fmaf(v, v, s);
    }
#pragma unroll
    for (int off = 16; off > 0; off >>= 1)
        s += __shfl_down_sync(0xffffffffu, s, off);
    __shared__ float ws[4];
    if ((threadIdx.x & 31) == 0) ws[threadIdx.x >> 5] = s;
    __syncthreads();
    if (threadIdx.x == 0) *o = ws[0] + ws[1] + ws[2] + ws[3];
}

// ---------------------------------------------------------------------------
// Pass 2: S = Q @ K^T with epilogue logits = (2*s - qq - kk) / 13
// 128x128x16 tiles, 256 threads, 8x8 per-thread microkernel, double buffered.
// Both operands are K-major (D contiguous). Writes into log_attn region.
// ---------------------------------------------------------------------------
#define BM 128
#define BN 128
#define BK 16

__global__ __launch_bounds__(256, 2)
void gemm_qk_kernel(const float* __restrict__ Q, const float* __restrict__ K,
                    float* __restrict__ logits) {
    int b = blockIdx.z;
    int m0 = blockIdx.y * BM;
    int n0 = blockIdx.x * BN;
    const float* Ab = Q + (size_t)b * LQ * DIM;
    const float* Bb = K + (size_t)b * LK * DIM;
    float* Cb = logits + (size_t)b * LQ * LK;

    __shared__ float As[2][BK][BM];
    __shared__ float Bs[2][BK][BN];

    int t = threadIdx.x;
    int tx = t & 15;        // 0..15 -> 8 cols each
    int ty = t >> 4;        // 0..15 -> 8 rows each

    // tile-load mapping: 128 rows x 4 float4 (16 k) per tile
    int r0 = t >> 2;        // 0..63
    int c0 = t & 3;         // float4 column (k/4)

    float acc[8][8];
#pragma unroll
    for (int i = 0; i < 8; i++)
#pragma unroll
        for (int j = 0; j < 8; j++) acc[i][j] = 0.f;

    // prologue: load k-tile 0 into buffer 0
    {
        const float* ap = Ab + (size_t)(m0 + r0) * DIM + c0 * 4;
        float4 a0 = *(const float4*)ap;
        float4 a1 = *(const float4*)(ap + (size_t)64 * DIM);
        const float* bp = Bb + (size_t)(n0 + r0) * DIM + c0 * 4;
        float4 b0 = *(const float4*)bp;
        float4 b1 = *(const float4*)(bp + (size_t)64 * DIM);
        As[0][c0 * 4 + 0][r0] = a0.x; As[0][c0 * 4 + 1][r0] = a0.y;
        As[0][c0 * 4 + 2][r0] = a0.z; As[0][c0 * 4 + 3][r0] = a0.w;
        As[0][c0 * 4 + 0][r0 + 64] = a1.x; As[0][c0 * 4 + 1][r0 + 64] = a1.y;
        As[0][c0 * 4 + 2][r0 + 64] = a1.z; As[0][c0 * 4 + 3][r0 + 64] = a1.w;
        Bs[0][c0 * 4 + 0][r0] = b0.x; Bs[0][c0 * 4 + 1][r0] = b0.y;
        Bs[0][c0 * 4 + 2][r0] = b0.z; Bs[0][c0 * 4 + 3][r0] = b0.w;
        Bs[0][c0 * 4 + 0][r0 + 64] = b1.x; Bs[0][c0 * 4 + 1][r0 + 64] = b1.y;
        Bs[0][c0 * 4 + 2][r0 + 64] = b1.z; Bs[0][c0 * 4 + 3][r0 + 64] = b1.w;
    }
    __syncthreads();

    const int KT = DIM / BK;   // 40
    for (int kt = 0; kt < KT; kt++) {
        int cur = kt & 1, nxt = cur ^ 1;
        float4 na0, na1, nb0, nb1;
        bool more = (kt + 1 < KT);
        if (more) {
            const float* ap = Ab + (size_t)(m0 + r0) * DIM + (kt + 1) * BK + c0 * 4;
            na0 = *(const float4*)ap;
            na1 = *(const float4*)(ap + (size_t)64 * DIM);
            const float* bp = Bb + (size_t)(n0 + r0) * DIM + (kt + 1) * BK + c0 * 4;
            nb0 = *(const float4*)bp;
            nb1 = *(const float4*)(bp + (size_t)64 * DIM);
        }
#pragma unroll
        for (int kk = 0; kk < BK; kk++) {
            float a[8], bb[8];
            *(float4*)&a[0] = *(const float4*)&As[cur][kk][ty * 8];
            *(float4*)&a[4] = *(const float4*)&As[cur][kk][ty * 8 + 4];
            *(float4*)&bb[0] = *(const float4*)&Bs[cur][kk][tx * 8];
            *(float4*)&bb[4] = *(const float4*)&Bs[cur][kk][tx * 8 + 4];
#pragma unroll
            for (int i = 0; i < 8; i++)
#pragma unroll
                for (int j = 0; j < 8; j++)
                    acc[i][j] = fmaf(a[i], bb[j], acc[i][j]);
        }
        if (more) {
            As[nxt][c0 * 4 + 0][r0] = na0.x; As[nxt][c0 * 4 + 1][r0] = na0.y;
            As[nxt][c0 * 4 + 2][r0] = na0.z; As[nxt][c0 * 4 + 3][r0] = na0.w;
            As[nxt][c0 * 4 + 0][r0 + 64] = na1.x; As[nxt][c0 * 4 + 1][r0 + 64] = na1.y;
            As[nxt][c0 * 4 + 2][r0 + 64] = na1.z; As[nxt][c0 * 4 + 3][r0 + 64] = na1.w;
            Bs[nxt][c0 * 4 + 0][r0] = nb0.x; Bs[nxt][c0 * 4 + 1][r0] = nb0.y;
            Bs[nxt][c0 * 4 + 2][r0] = nb0.z; Bs[nxt][c0 * 4 + 3][r0] = nb0.w;
            Bs[nxt][c0 * 4 + 0][r0 + 64] = nb1.x; Bs[nxt][c0 * 4 + 1][r0 + 64] = nb1.y;
            Bs[nxt][c0 * 4 + 2][r0 + 64] = nb1.z; Bs[nxt][c0 * 4 + 3][r0 + 64] = nb1.w;
            __syncthreads();
        }
    }

    // epilogue: logits = (2*s - qq - kk) / 13
    float qrow[8], kcol[8];
#pragma unroll
    for (int i = 0; i < 8; i++) qrow[i] = g_qq[b * LQ + m0 + ty * 8 + i];
#pragma unroll
    for (int j = 0; j < 8; j++) kcol[j] = g_kk[b * LK + n0 + tx * 8 + j];

#pragma unroll
    for (int i = 0; i < 8; i++) {
        float4 v0, v1;
        float* vp0 = &v0.x;
        float* vp1 = &v1.x;
#pragma unroll
        for (int j = 0; j < 4; j++)
            vp0[j] = (2.f * acc[i][j] - qrow[i] - kcol[j]) * INV_TEMP;
#pragma unroll
        for (int j = 0; j < 4; j++)
            vp1[j] = (2.f * acc[i][4 + j] - qrow[i] - kcol[4 + j]) * INV_TEMP;
        float* cp = Cb + (size_t)(m0 + ty * 8 + i) * LK + n0 + tx * 8;
        *(float4*)cp = v0;
        *(float4*)(cp + 4) = v1;
    }
}

// ---------------------------------------------------------------------------
// Pass 3: row softmax. Reads logits (in log_attn region), rewrites log_attn
// in place and writes attn = exp(log_attn). One block (256 thr) per row.
// ---------------------------------------------------------------------------
__global__ __launch_bounds__(256)
void softmax_kernel(float* __restrict__ logattn, float* __restrict__ attn) {
    size_t row = blockIdx.x;
    float* lp = logattn + row * LK;
    float* ap = attn + row * LK;
    int t = threadIdx.x;

    float x[8];
#pragma unroll
    for (int j = 0; j < 8; j++) x[j] = lp[t + j * 256];

    float m = x[0];
#pragma unroll
    for (int j = 1; j < 8; j++) m = fmaxf(m, x[j]);
#pragma unroll
    for (int off = 16; off > 0; off >>= 1)
        m = fmaxf(m, __shfl_xor_sync(0xffffffffu, m, off));
    __shared__ float red[8];
    __shared__ float bval;
    if ((t & 31) == 0) red[t >> 5] = m;
    __syncthreads();
    if (t == 0) {
        float mm = red[0];
#pragma unroll
        for (int w = 1; w < 8; w++) mm = fmaxf(mm, red[w]);
        bval = mm;
    }
    __syncthreads();
    m = bval;

    float s = 0.f;
#pragma unroll
    for (int j = 0; j < 8; j++) s += expf(x[j] - m);
#pragma unroll
    for (int off = 16; off > 0; off >>= 1)
        s += __shfl_xor_sync(0xffffffffu, s, off);
    __syncthreads();
    if ((t & 31) == 0) red[t >> 5] = s;
    __syncthreads();
    if (t == 0) {
        float ss = 0.f;
#pragma unroll
        for (int w = 0; w < 8; w++) ss += red[w];
        bval = m + logf(ss);
    }
    __syncthreads();
    float lse = bval;

#pragma unroll
    for (int j = 0; j < 8; j++) {
        float la = x[j] - lse;
        lp[t + j * 256] = la;
        ap[t + j * 256] = expf(la);
    }
}

// ---------------------------------------------------------------------------
// Pass 4: output = attn @ V.  M=2048, N=640, K=2048.
// A (attn) is K-major; B (v) is N-major (direct copy, no transpose).
// ---------------------------------------------------------------------------
__global__ __launch_bounds__(256, 2)
void gemm_av_kernel(const float* __restrict__ A, const float* __restrict__ V,
                    float* __restrict__ O) {
    int b = blockIdx.z;
    int m0 = blockIdx.y * BM;
    int n0 = blockIdx.x * BN;
    const float* Ab = A + (size_t)b * LQ * LK;
    const float* Bb = V + (size_t)b * LK * DIM;
    float* Cb = O + (size_t)b * LQ * DIM;

    __shared__ float As[2][BK][BM];
    __shared__ float Bs[2][BK][BN];

    int t = threadIdx.x;
    int tx = t & 15;
    int ty = t >> 4;

    // A tile mapping (transpose store): 128 rows x 4 f4 cols
    int ar = t >> 2;
    int ac = t & 3;
    // B tile mapping (direct): 16 rows x 32 f4 cols
    int br = t >> 5;       // 0..7 (and +8 for second half)
    int bc = t & 31;       // f4 column

    float acc[8][8];
#pragma unroll
    for (int i = 0; i < 8; i++)
#pragma unroll
        for (int j = 0; j < 8; j++) acc[i][j] = 0.f;

    {
        const float* apt = Ab + (size_t)(m0 + ar) * LK + ac * 4;
        float4 a0 = *(const float4*)apt;
        float4 a1 = *(const float4*)(apt + (size_t)64 * LK);
        const float* bpt = Bb + (size_t)br * DIM + n0 + bc * 4;
        float4 b0 = *(const float4*)bpt;
        float4 b1 = *(const float4*)(bpt + (size_t)8 * DIM);
        As[0][ac * 4 + 0][ar] = a0.x; As[0][ac * 4 + 1][ar] = a0.y;
        As[0][ac * 4 + 2][ar] = a0.z; As[0][ac * 4 + 3][ar] = a0.w;
        As[0][ac * 4 + 0][ar + 64] = a1.x; As[0][ac * 4 + 1][ar + 64] = a1.y;
        As[0][ac * 4 + 2][ar + 64] = a1.z; As[0][ac * 4 + 3][ar + 64] = a1.w;
        *(float4*)&Bs[0][br][bc * 4] = b0;
        *(float4*)&Bs[0][br + 8][bc * 4] = b1;
    }
    __syncthreads();

    const int KT = LK / BK;   // 128
    for (int kt = 0; kt < KT; kt++) {
        int cur = kt & 1, nxt = cur ^ 1;
        float4 na0, na1, nb0, nb1;
        bool more = (kt + 1 < KT);
        if (more) {
            const float* apt = Ab + (size_t)(m0 + ar) * LK + (kt + 1) * BK + ac * 4;
            na0 = *(const float4*)apt;
            na1 = *(const float4*)(apt + (size_t)64 * LK);
            const float* bpt = Bb + (size_t)((kt + 1) * BK + br) * DIM + n0 + bc * 4;
            nb0 = *(const float4*)bpt;
            nb1 = *(const float4*)(bpt + (size_t)8 * DIM);
        }
#pragma unroll
        for (int kk = 0; kk < BK; kk++) {
            float a[8], bb[8];
            *(float4*)&a[0] = *(const float4*)&As[cur][kk][ty * 8];
            *(float4*)&a[4] = *(const float4*)&As[cur][kk][ty * 8 + 4];
            *(float4*)&bb[0] = *(const float4*)&Bs[cur][kk][tx * 8];
            *(float4*)&bb[4] = *(const float4*)&Bs[cur][kk][tx * 8 + 4];
#pragma unroll
            for (int i = 0; i < 8; i++)
#pragma unroll
                for (int j = 0; j < 8; j++)
                    acc[i][j] = fmaf(a[i], bb[j], acc[i][j]);
        }
        if (more) {
            As[nxt][ac * 4 + 0][ar] = na0.x; As[nxt][ac * 4 + 1][ar] = na0.y;
            As[nxt][ac * 4 + 2][ar] = na0.z; As[nxt][ac * 4 + 3][ar] = na0.w;
            As[nxt][ac * 4 + 0][ar + 64] = na1.x; As[nxt][ac * 4 + 1][ar + 64] = na1.y;
            As[nxt][ac * 4 + 2][ar + 64] = na1.z; As[nxt][ac * 4 + 3][ar + 64] = na1.w;
            *(float4*)&Bs[nxt][br][bc * 4] = nb0;
            *(float4*)&Bs[nxt][br + 8][bc * 4] = nb1;
            __syncthreads();
        }
    }

#pragma unroll
    for (int i = 0; i < 8; i++) {
        float* cp = Cb + (size_t)(m0 + ty * 8 + i) * DIM + n0 + tx * 8;
        *(float4*)cp = *(float4*)&acc[i][0];
        *(float4*)(cp + 4) = *(float4*)&acc[i][4];
    }
}

// ---------------------------------------------------------------------------
extern "C" void kernel_launch(void* const* d_in, const int* in_sizes, int n_in,
                              void* d_out, int out_size) {
    const float* q = (const float*)d_in[0];
    const float* k = (const float*)d_in[1];
    const float* v = (const float*)d_in[2];

    float* out = (float*)d_out;                                   // (B, Lq, D)
    float* attn = out + (size_t)BATCH * LQ * DIM;                 // (B, Lq, Lk)
    float* logattn = attn + (size_t)BATCH * LQ * LK;              // (B, Lq, Lk)

    // Pass 1: row sums of squares
    sumsq_kernel<<<2 * BATCH * LQ, 128>>>(q, k);

    // Pass 2: logits into log_attn region
    dim3 g1(LK / BN, LQ / BM, BATCH);
    gemm_qk_kernel<<<g1, 256>>>(q, k, logattn);

    // Pass 3: softmax (in-place log_attn, writes attn)
    softmax_kernel<<<BATCH * LQ, 256>>>(logattn, attn);

    // Pass 4: output = attn @ V
    dim3 g2(DIM / BN, LQ / BM, BATCH);
    gemm_av_kernel<<<g2, 256>>>(attn, v, out);
}

// round 5
// speedup vs baseline: 1.9339x; 1.9326x over previous
#include <cuda_runtime.h>
#include <cuda_bf16.h>
#include <math.h>
#include <stdint.h>

#define BATCH 8
#define LQ 2048
#define LK 2048
#define DIM 640
#define INV_TEMP (1.0f / 13.0f)

// ---------------------------------------------------------------------------
// Device scratch (allocation-free rule: __device__ globals)
// split-bf16 concatenated operands: row-major, K' = 2*K (first K = hi, next K = lo)
// ---------------------------------------------------------------------------
__device__ float g_qq[BATCH * LQ];
__device__ float g_kk[BATCH * LK];
__device__ __nv_bfloat16 g_qcat[(size_t)BATCH * LQ * 2 * DIM];   // [B*LQ, 1280]
__device__ __nv_bfloat16 g_kcat[(size_t)BATCH * LK * 2 * DIM];   // [B*LK, 1280]
__device__ __nv_bfloat16 g_vt[(size_t)BATCH * DIM * 2 * LK];     // [B*DIM, 4096] (v^T)
__device__ __nv_bfloat16 g_acat[(size_t)BATCH * LQ * 2 * LK];    // [B*LQ, 4096]

// ---------------------------------------------------------------------------
// helpers
// ---------------------------------------------------------------------------
__device__ __forceinline__ uint32_t smem_u32(const void* p) {
    uint32_t a;
    asm("{ .reg .u64 t; cvta.to.shared.u64 t, %1; cvt.u32.u64 %0, t; }" : "=r"(a) : "l"(p));
    return a;
}
__device__ __forceinline__ void cp16(uint32_t dst, const void* src) {
    asm volatile("cp.async.cg.shared.global [%0], [%1], 16;" :: "r"(dst), "l"(src) : "memory");
}
__device__ __forceinline__ void ldmx4(uint32_t* r, uint32_t addr) {
    asm volatile("ldmatrix.sync.aligned.m8n8.x4.shared.b16 {%0,%1,%2,%3}, [%4];"
                 : "=r"(r[0]), "=r"(r[1]), "=r"(r[2]), "=r"(r[3]) : "r"(addr));
}
__device__ __forceinline__ void mma16816(float* c, const uint32_t* a, uint32_t b0, uint32_t b1) {
    asm volatile(
        "mma.sync.aligned.m16n8k16.row.col.f32.bf16.bf16.f32 "
        "{%0,%1,%2,%3}, {%4,%5,%6,%7}, {%8,%9}, {%0,%1,%2,%3};"
        : "+f"(c[0]), "+f"(c[1]), "+f"(c[2]), "+f"(c[3])
        : "r"(a[0]), "r"(a[1]), "r"(a[2]), "r"(a[3]), "r"(b0), "r"(b1));
}

// ---------------------------------------------------------------------------
// Pass 0a: q,k -> hi/lo bf16 concatenated arrays + row sum-of-squares
// ---------------------------------------------------------------------------
__global__ __launch_bounds__(128)
void conv_qk_kernel(const float* __restrict__ q, const float* __restrict__ k) {
    int row = blockIdx.x;
    bool isQ = row < BATCH * LQ;
    int r = isQ ? row : row - BATCH * LQ;
    const float* src = (isQ ? q : k) + (size_t)r * DIM;
    __nv_bfloat16* dst = (isQ ? g_qcat : g_kcat) + (size_t)r * 2 * DIM;

    float s = 0.f;
    for (int i = threadIdx.x; i < DIM; i += 128) {
        float x = src[i];
        s = fmaf(x, x, s);
        __nv_bfloat16 h = __float2bfloat16(x);
        dst[i] = h;
        dst[DIM + i] = __float2bfloat16(x - __bfloat162float(h));
    }
#pragma unroll
    for (int off = 16; off > 0; off >>= 1)
        s += __shfl_down_sync(0xffffffffu, s, off);
    __shared__ float ws[4];
    if ((threadIdx.x & 31) == 0) ws[threadIdx.x >> 5] = s;
    __syncthreads();
    if (threadIdx.x == 0) {
        float t = ws[0] + ws[1] + ws[2] + ws[3];
        if (isQ) g_qq[r] = t; else g_kk[r] = t;
    }
}

// ---------------------------------------------------------------------------
// Pass 0b: v -> transposed hi/lo bf16: g_vt[(b*DIM+d), k](hi), [.., LK+k](lo)
// ---------------------------------------------------------------------------
__global__ __launch_bounds__(256)
void conv_v_kernel(const float* __restrict__ v) {
    __shared__ float tile[32][33];
    int b = blockIdx.z;
    int k0 = blockIdx.x * 32;
    int d0 = blockIdx.y * 32;
    int tx = threadIdx.x, ty = threadIdx.y;
#pragma unroll
    for (int i = ty; i < 32; i += 8)
        tile[i][tx] = v[((size_t)b * LK + k0 + i) * DIM + d0 + tx];
    __syncthreads();
#pragma unroll
    for (int i = ty; i < 32; i += 8) {
        float x = tile[tx][i];  // v[k0+tx][d0+i]
        __nv_bfloat16 h = __float2bfloat16(x);
        __nv_bfloat16 l = __float2bfloat16(x - __bfloat162float(h));
        size_t rowbase = ((size_t)b * DIM + d0 + i) * (2 * LK);
        g_vt[rowbase + k0 + tx] = h;
        g_vt[rowbase + LK + k0 + tx] = l;
    }
}

// ---------------------------------------------------------------------------
// mma.sync split-bf16 GEMM. CTA tile 128x128, 8 warps (2m x 4n), warp 64x32.
// A rows: [hi(0:HALFK) | lo(HALFK:2*HALFK)], same for B; 3 passes hh, lh, hl.
// LOGITS: C = (2*acc - qq[m] - kk[n]) / 13.
// ---------------------------------------------------------------------------
template <int HALFK, bool LOGITS, int BROWS>
__global__ __launch_bounds__(256)
void gemm_mma_kernel(const __nv_bfloat16* __restrict__ Ag,
                     const __nv_bfloat16* __restrict__ Bg,
                     float* __restrict__ C, int ldc) {
    constexpr int STRIDE = 2 * HALFK;
    constexpr int KCH = HALFK / 32;     // 32-wide k chunks per pass
    constexpr int NCH = 3 * KCH;

    // [stage][row][32k] bf16, 64B rows, XOR swizzle on 16B chunks
    __shared__ __nv_bfloat16 As[3][128 * 32];
    __shared__ __nv_bfloat16 Bs[3][128 * 32];

    const uint32_t uA = smem_u32(As);
    const uint32_t uB = smem_u32(Bs);

    int t = threadIdx.x;
    int wid = t >> 5, lane = t & 31;
    int warp_m = wid >> 2;       // 0..1
    int warp_n = wid & 3;        // 0..3
    int b = blockIdx.z;
    int m0 = blockIdx.y * 128;
    int n0 = blockIdx.x * 128;
    size_t arow0 = (size_t)b * LQ + m0;
    size_t brow0 = (size_t)b * BROWS + n0;

    // cp.async load mapping: piece p in [0,512): row=p>>2, 16B chunk c=p&3
    int p0 = t, p1 = t + 256;

    auto load_chunk = [&](int ck, int st) {
        int pass = ck / KCH;
        int kc = (ck - pass * KCH) * 32;
        int aoff = (pass == 1) ? HALFK : 0;
        int boff = (pass == 2) ? HALFK : 0;
        const __nv_bfloat16* ab = Ag + arow0 * STRIDE + aoff + kc;
        const __nv_bfloat16* bb = Bg + brow0 * STRIDE + boff + kc;
#pragma unroll
        for (int h = 0; h < 2; h++) {
            int p = h ? p1 : p0;
            int row = p >> 2, c = p & 3;
            int cs = c ^ ((row >> 1) & 3);
            cp16(uA + st * 8192 + row * 64 + cs * 16, ab + (size_t)row * STRIDE + c * 8);
            cp16(uB + st * 8192 + row * 64 + cs * 16, bb + (size_t)row * STRIDE + c * 8);
        }
    };

    float acc[4][4][4];
#pragma unroll
    for (int i = 0; i < 4; i++)
#pragma unroll
        for (int j = 0; j < 4; j++)
#pragma unroll
            for (int u = 0; u < 4; u++) acc[i][j][u] = 0.f;

    load_chunk(0, 0);
    asm volatile("cp.async.commit_group;" ::: "memory");
    load_chunk(1, 1);
    asm volatile("cp.async.commit_group;" ::: "memory");

    int lr16 = lane & 15;          // row within 16-row tile
    int hi16 = lane >> 4;          // 16B chunk selector within k16

    for (int s = 0; s < NCH; s++) {
        if (s + 2 < NCH) load_chunk(s + 2, (s + 2) % 3);
        asm volatile("cp.async.commit_group;" ::: "memory");
        asm volatile("cp.async.wait_group 2;" ::: "memory");
        __syncthreads();

        int st = s % 3;
        uint32_t aBase = uA + st * 8192;
        uint32_t bBase = uB + st * 8192;
#pragma unroll
        for (int ks = 0; ks < 2; ks++) {
            uint32_t afr[4][4];
#pragma unroll
            for (int mt = 0; mt < 4; mt++) {
                int row = warp_m * 64 + mt * 16 + lr16;
                int c = ks * 2 + hi16;
                int cs = c ^ ((row >> 1) & 3);
                ldmx4(afr[mt], aBase + row * 64 + cs * 16);
            }
            uint32_t bfr[2][4];
#pragma unroll
            for (int np = 0; np < 2; np++) {
                int row = warp_n * 32 + np * 16 + lr16;
                int c = ks * 2 + hi16;
                int cs = c ^ ((row >> 1) & 3);
                ldmx4(bfr[np], bBase + row * 64 + cs * 16);
            }
#pragma unroll
            for (int mt = 0; mt < 4; mt++)
#pragma unroll
                for (int nt = 0; nt < 4; nt++) {
                    int np = nt >> 1, sel = nt & 1;
                    mma16816(acc[mt][nt], afr[mt], bfr[np][sel], bfr[np][sel + 2]);
                }
        }
        __syncthreads();
    }

    // ---------------- epilogue ----------------
    int lr = lane >> 2;            // 0..7
    int lc = (lane & 3) * 2;       // 0,2,4,6
#pragma unroll
    for (int mt = 0; mt < 4; mt++) {
#pragma unroll
        for (int h = 0; h < 2; h++) {
            int row = m0 + warp_m * 64 + mt * 16 + h * 8 + lr;
            size_t crow = (size_t)b * LQ + row;
            float qqv = LOGITS ? g_qq[crow] : 0.f;
            float* cp = C + crow * ldc + n0 + warp_n * 32 + lc;
#pragma unroll
            for (int nt = 0; nt < 4; nt++) {
                float v0 = acc[mt][nt][h * 2 + 0];
                float v1 = acc[mt][nt][h * 2 + 1];
                if (LOGITS) {
                    int col = b * LK + n0 + warp_n * 32 + nt * 8 + lc;
                    v0 = (2.f * v0 - qqv - g_kk[col]) * INV_TEMP;
                    v1 = (2.f * v1 - qqv - g_kk[col + 1]) * INV_TEMP;
                }
                float2 w; w.x = v0; w.y = v1;
                *(float2*)(cp + nt * 8) = w;
            }
        }
    }
}

// ---------------------------------------------------------------------------
// Pass 3: row softmax; rewrites log_attn in place, writes attn fp32 and
// attn hi/lo bf16 (g_acat) for the AV GEMM.
// ---------------------------------------------------------------------------
__global__ __launch_bounds__(256)
void softmax_kernel(float* __restrict__ logattn, float* __restrict__ attn) {
    size_t row = blockIdx.x;
    float* lp = logattn + row * LK;
    float* ap = attn + row * LK;
    __nv_bfloat16* acp = g_acat + row * (size_t)(2 * LK);
    int t = threadIdx.x;

    float x[8];
#pragma unroll
    for (int j = 0; j < 8; j++) x[j] = lp[t + j * 256];

    float m = x[0];
#pragma unroll
    for (int j = 1; j < 8; j++) m = fmaxf(m, x[j]);
#pragma unroll
    for (int off = 16; off > 0; off >>= 1)
        m = fmaxf(m, __shfl_xor_sync(0xffffffffu, m, off));
    __shared__ float red[8];
    __shared__ float bval;
    if ((t & 31) == 0) red[t >> 5] = m;
    __syncthreads();
    if (t == 0) {
        float mm = red[0];
#pragma unroll
        for (int w = 1; w < 8; w++) mm = fmaxf(mm, red[w]);
        bval = mm;
    }
    __syncthreads();
    m = bval;

    float s = 0.f;
#pragma unroll
    for (int j = 0; j < 8; j++) s += expf(x[j] - m);
#pragma unroll
    for (int off = 16; off > 0; off >>= 1)
        s += __shfl_xor_sync(0xffffffffu, s, off);
    __syncthreads();
    if ((t & 31) == 0) red[t >> 5] = s;
    __syncthreads();
    if (t == 0) {
        float ss = 0.f;
#pragma unroll
        for (int w = 0; w < 8; w++) ss += red[w];
        bval = m + logf(ss);
    }
    __syncthreads();
    float lse = bval;

#pragma unroll
    for (int j = 0; j < 8; j++) {
        int idx = t + j * 256;
        float la = x[j] - lse;
        float a = expf(la);
        lp[idx] = la;
        ap[idx] = a;
        __nv_bfloat16 h = __float2bfloat16(a);
        acp[idx] = h;
        acp[LK + idx] = __float2bfloat16(a - __bfloat162float(h));
    }
}

// ---------------------------------------------------------------------------
extern "C" void kernel_launch(void* const* d_in, const int* in_sizes, int n_in,
                              void* d_out, int out_size) {
    const float* q = (const float*)d_in[0];
    const float* k = (const float*)d_in[1];
    const float* v = (const float*)d_in[2];

    float* out = (float*)d_out;                            // (B, Lq, D)
    float* attn = out + (size_t)BATCH * LQ * DIM;          // (B, Lq, Lk)
    float* logattn = attn + (size_t)BATCH * LQ * LK;       // (B, Lq, Lk)

    // Pass 0: conversions + row sums of squares
    conv_qk_kernel<<<2 * BATCH * LQ, 128>>>(q, k);
    {
        dim3 g(LK / 32, DIM / 32, BATCH);
        conv_v_kernel<<<g, dim3(32, 8)>>>(v);
    }

    // Pass 1: logits (into log_attn region): A=qcat [B*LQ,1280], B=kcat [B*LK,1280]
    {
        __nv_bfloat16* qc; cudaGetSymbolAddress((void**)&qc, g_qcat);
        __nv_bfloat16* kc; cudaGetSymbolAddress((void**)&kc, g_kcat);
        dim3 g(LK / 128, LQ / 128, BATCH);
        gemm_mma_kernel<DIM, true, LK><<<g, 256>>>(qc, kc, logattn, LK);
    }

    // Pass 2: softmax (in-place log_attn, attn fp32, attn bf16 hi/lo)
    softmax_kernel<<<BATCH * LQ, 256>>>(logattn, attn);

    // Pass 3: out = attn @ V: A=acat [B*LQ,4096], B=vt [B*DIM,4096]
    {
        __nv_bfloat16* ac; cudaGetSymbolAddress((void**)&ac, g_acat);
        __nv_bfloat16* vt; cudaGetSymbolAddress((void**)&vt, g_vt);
        dim3 g(DIM / 128, LQ / 128, BATCH);
        gemm_mma_kernel<LK, false, DIM><<<g, 256>>>(ac, vt, out, DIM);
    }
}

// round 6
// speedup vs baseline: 1.9917x; 1.0299x over previous
#include <cuda_runtime.h>
#include <cuda_bf16.h>
#include <math.h>
#include <stdint.h>

#define BATCH 8
#define LQ 2048
#define LK 2048
#define DIM 640
#define INV_TEMP (1.0f / 13.0f)

// ---------------------------------------------------------------------------
// Device scratch (allocation-free rule: __device__ globals)
// split-bf16 concatenated operands: row-major, K' = 2*K (first K = hi, next K = lo)
// ---------------------------------------------------------------------------
__device__ float g_qq[BATCH * LQ];
__device__ float g_kk[BATCH * LK];
__device__ __nv_bfloat16 g_qcat[(size_t)BATCH * LQ * 2 * DIM];   // [B*LQ, 1280]
__device__ __nv_bfloat16 g_kcat[(size_t)BATCH * LK * 2 * DIM];   // [B*LK, 1280]
__device__ __nv_bfloat16 g_vt[(size_t)BATCH * DIM * 2 * LK];     // [B*DIM, 4096] (v^T)
__device__ __nv_bfloat16 g_acat[(size_t)BATCH * LQ * 2 * LK];    // [B*LQ, 4096]

// ---------------------------------------------------------------------------
// helpers
// ---------------------------------------------------------------------------
__device__ __forceinline__ uint32_t smem_u32(const void* p) {
    uint32_t a;
    asm("{ .reg .u64 t; cvta.to.shared.u64 t, %1; cvt.u32.u64 %0, t; }" : "=r"(a) : "l"(p));
    return a;
}
__device__ __forceinline__ void cp16(uint32_t dst, const void* src) {
    asm volatile("cp.async.cg.shared.global [%0], [%1], 16;" :: "r"(dst), "l"(src) : "memory");
}
__device__ __forceinline__ void ldmx4(uint32_t* r, uint32_t addr) {
    asm volatile("ldmatrix.sync.aligned.m8n8.x4.shared.b16 {%0,%1,%2,%3}, [%4];"
                 : "=r"(r[0]), "=r"(r[1]), "=r"(r[2]), "=r"(r[3]) : "r"(addr));
}
__device__ __forceinline__ void mma16816(float* c, const uint32_t* a, uint32_t b0, uint32_t b1) {
    asm volatile(
        "mma.sync.aligned.m16n8k16.row.col.f32.bf16.bf16.f32 "
        "{%0,%1,%2,%3}, {%4,%5,%6,%7}, {%8,%9}, {%0,%1,%2,%3};"
        : "+f"(c[0]), "+f"(c[1]), "+f"(c[2]), "+f"(c[3])
        : "r"(a[0]), "r"(a[1]), "r"(a[2]), "r"(a[3]), "r"(b0), "r"(b1));
}

// ---------------------------------------------------------------------------
// Pass 0a: q,k -> hi/lo bf16 concatenated arrays + row sum-of-squares
// ---------------------------------------------------------------------------
__global__ __launch_bounds__(128)
void conv_qk_kernel(const float* __restrict__ q, const float* __restrict__ k) {
    int row = blockIdx.x;
    bool isQ = row < BATCH * LQ;
    int r = isQ ? row : row - BATCH * LQ;
    const float* src = (isQ ? q : k) + (size_t)r * DIM;
    __nv_bfloat16* dst = (isQ ? g_qcat : g_kcat) + (size_t)r * 2 * DIM;

    float s = 0.f;
    for (int i = threadIdx.x; i < DIM; i += 128) {
        float x = src[i];
        s = fmaf(x, x, s);
        __nv_bfloat16 h = __float2bfloat16(x);
        dst[i] = h;
        dst[DIM + i] = __float2bfloat16(x - __bfloat162float(h));
    }
#pragma unroll
    for (int off = 16; off > 0; off >>= 1)
        s += __shfl_down_sync(0xffffffffu, s, off);
    __shared__ float ws[4];
    if ((threadIdx.x & 31) == 0) ws[threadIdx.x >> 5] = s;
    __syncthreads();
    if (threadIdx.x == 0) {
        float t = ws[0] + ws[1] + ws[2] + ws[3];
        if (isQ) g_qq[r] = t; else g_kk[r] = t;
    }
}

// ---------------------------------------------------------------------------
// Pass 0b: v -> transposed hi/lo bf16: g_vt[(b*DIM+d), k](hi), [.., LK+k](lo)
// ---------------------------------------------------------------------------
__global__ __launch_bounds__(256)
void conv_v_kernel(const float* __restrict__ v) {
    __shared__ float tile[32][33];
    int b = blockIdx.z;
    int k0 = blockIdx.x * 32;
    int d0 = blockIdx.y * 32;
    int tx = threadIdx.x, ty = threadIdx.y;
#pragma unroll
    for (int i = ty; i < 32; i += 8)
        tile[i][tx] = v[((size_t)b * LK + k0 + i) * DIM + d0 + tx];
    __syncthreads();
#pragma unroll
    for (int i = ty; i < 32; i += 8) {
        float x = tile[tx][i];  // v[k0+tx][d0+i]
        __nv_bfloat16 h = __float2bfloat16(x);
        __nv_bfloat16 l = __float2bfloat16(x - __bfloat162float(h));
        size_t rowbase = ((size_t)b * DIM + d0 + i) * (2 * LK);
        g_vt[rowbase + k0 + tx] = h;
        g_vt[rowbase + LK + k0 + tx] = l;
    }
}

// ---------------------------------------------------------------------------
// mma.sync split-bf16 GEMM. CTA tile MT x NT, warps of 64x64 in (MT/64, NT/64).
// A rows: [hi(0:HALFK) | lo(HALFK:2*HALFK)], same for B; 3 passes hh, lh, hl.
// NSTAGE-deep cp.async pipeline, 32-wide k chunks.
// LOGITS: C = (2*acc - qq[m] - kk[n]) / 13.
// ---------------------------------------------------------------------------
template <int MT, int NT, int HALFK, bool LOGITS, int BROWS, int NSTAGE>
__global__ __launch_bounds__((MT / 64) * (NT / 64) * 32, 256 / ((MT / 64) * (NT / 64) * 32))
void gemm_mma_kernel(const __nv_bfloat16* __restrict__ Ag,
                     const __nv_bfloat16* __restrict__ Bg,
                     float* __restrict__ C, int ldc) {
    constexpr int WM = MT / 64;
    constexpr int WN = NT / 64;
    constexpr int NTHR = WM * WN * 32;
    constexpr int STRIDE = 2 * HALFK;
    constexpr int KCH = HALFK / 32;     // 32-wide k chunks per pass
    constexpr int NCH = 3 * KCH;
    constexpr int ABYTES = MT * 64;     // MT rows x 32 bf16
    constexpr int BBYTES = NT * 64;

    extern __shared__ char dsm[];
    const uint32_t uA = smem_u32(dsm);
    const uint32_t uB = uA + NSTAGE * ABYTES;

    int t = threadIdx.x;
    int wid = t >> 5, lane = t & 31;
    int warp_m = wid % WM;
    int warp_n = wid / WM;
    int b = blockIdx.z;
    int m0 = blockIdx.y * MT;
    int n0 = blockIdx.x * NT;
    size_t arow0 = (size_t)b * LQ + m0;
    size_t brow0 = (size_t)b * BROWS + n0;

    auto load_chunk = [&](int ck, int st) {
        int pass = ck / KCH;
        int kc = (ck - pass * KCH) * 32;
        int aoff = (pass == 1) ? HALFK : 0;
        int boff = (pass == 2) ? HALFK : 0;
        const __nv_bfloat16* ab = Ag + arow0 * STRIDE + aoff + kc;
        const __nv_bfloat16* bb = Bg + brow0 * STRIDE + boff + kc;
#pragma unroll
        for (int p = t; p < MT * 4; p += NTHR) {
            int row = p >> 2, c = p & 3;
            int cs = c ^ ((row >> 1) & 3);
            cp16(uA + st * ABYTES + row * 64 + cs * 16, ab + (size_t)row * STRIDE + c * 8);
        }
#pragma unroll
        for (int p = t; p < NT * 4; p += NTHR) {
            int row = p >> 2, c = p & 3;
            int cs = c ^ ((row >> 1) & 3);
            cp16(uB + st * BBYTES + row * 64 + cs * 16, bb + (size_t)row * STRIDE + c * 8);
        }
    };

    float acc[4][8][4];
#pragma unroll
    for (int i = 0; i < 4; i++)
#pragma unroll
        for (int j = 0; j < 8; j++)
#pragma unroll
            for (int u = 0; u < 4; u++) acc[i][j][u] = 0.f;

    // prologue
#pragma unroll
    for (int s = 0; s < NSTAGE - 1; s++) {
        if (s < NCH) load_chunk(s, s);
        asm volatile("cp.async.commit_group;" ::: "memory");
    }

    int lr16 = lane & 15;          // row within 16-row tile
    int hi16 = lane >> 4;          // 16B chunk selector within k16

    for (int s = 0; s < NCH; s++) {
        int pf = s + NSTAGE - 1;
        if (pf < NCH) load_chunk(pf, pf % NSTAGE);
        asm volatile("cp.async.commit_group;" ::: "memory");
        asm volatile("cp.async.wait_group %0;" :: "n"(NSTAGE - 1) : "memory");
        __syncthreads();

        int st = s % NSTAGE;
        uint32_t aBase = uA + st * ABYTES;
        uint32_t bBase = uB + st * BBYTES;
#pragma unroll
        for (int ks = 0; ks < 2; ks++) {
            int c = ks * 2 + hi16;
            uint32_t afr[4][4];
#pragma unroll
            for (int mt = 0; mt < 4; mt++) {
                int row = warp_m * 64 + mt * 16 + lr16;
                int cs = c ^ ((row >> 1) & 3);
                ldmx4(afr[mt], aBase + row * 64 + cs * 16);
            }
            uint32_t bfr[4][4];
#pragma unroll
            for (int np = 0; np < 4; np++) {
                int row = warp_n * 64 + np * 16 + lr16;
                int cs = c ^ ((row >> 1) & 3);
                ldmx4(bfr[np], bBase + row * 64 + cs * 16);
            }
#pragma unroll
            for (int mt = 0; mt < 4; mt++)
#pragma unroll
                for (int nt = 0; nt < 8; nt++) {
                    int np = nt >> 1, sel = nt & 1;
                    mma16816(acc[mt][nt], afr[mt], bfr[np][sel], bfr[np][sel + 2]);
                }
        }
        __syncthreads();
    }

    // ---------------- epilogue ----------------
    int lr = lane >> 2;            // 0..7
    int lc = (lane & 3) * 2;       // 0,2,4,6
#pragma unroll
    for (int mt = 0; mt < 4; mt++) {
#pragma unroll
        for (int h = 0; h < 2; h++) {
            int row = m0 + warp_m * 64 + mt * 16 + h * 8 + lr;
            size_t crow = (size_t)b * LQ + row;
            float qqv = LOGITS ? g_qq[crow] : 0.f;
            float* cp = C + crow * ldc + n0 + warp_n * 64 + lc;
#pragma unroll
            for (int nt = 0; nt < 8; nt++) {
                float v0 = acc[mt][nt][h * 2 + 0];
                float v1 = acc[mt][nt][h * 2 + 1];
                if (LOGITS) {
                    int col = b * LK + n0 + warp_n * 64 + nt * 8 + lc;
                    v0 = (2.f * v0 - qqv - g_kk[col]) * INV_TEMP;
                    v1 = (2.f * v1 - qqv - g_kk[col + 1]) * INV_TEMP;
                }
                float2 w; w.x = v0; w.y = v1;
                *(float2*)(cp + nt * 8) = w;
            }
        }
    }
}

// ---------------------------------------------------------------------------
// Pass 3: row softmax; rewrites log_attn in place, writes attn fp32 and
// attn hi/lo bf16 (g_acat) for the AV GEMM.
// ---------------------------------------------------------------------------
__global__ __launch_bounds__(256)
void softmax_kernel(float* __restrict__ logattn, float* __restrict__ attn) {
    size_t row = blockIdx.x;
    float* lp = logattn + row * LK;
    float* ap = attn + row * LK;
    __nv_bfloat16* acp = g_acat + row * (size_t)(2 * LK);
    int t = threadIdx.x;

    float x[8];
#pragma unroll
    for (int j = 0; j < 8; j++) x[j] = lp[t + j * 256];

    float m = x[0];
#pragma unroll
    for (int j = 1; j < 8; j++) m = fmaxf(m, x[j]);
#pragma unroll
    for (int off = 16; off > 0; off >>= 1)
        m = fmaxf(m, __shfl_xor_sync(0xffffffffu, m, off));
    __shared__ float red[8];
    __shared__ float bval;
    if ((t & 31) == 0) red[t >> 5] = m;
    __syncthreads();
    if (t == 0) {
        float mm = red[0];
#pragma unroll
        for (int w = 1; w < 8; w++) mm = fmaxf(mm, red[w]);
        bval = mm;
    }
    __syncthreads();
    m = bval;

    float s = 0.f;
#pragma unroll
    for (int j = 0; j < 8; j++) s += expf(x[j] - m);
#pragma unroll
    for (int off = 16; off > 0; off >>= 1)
        s += __shfl_xor_sync(0xffffffffu, s, off);
    __syncthreads();
    if ((t & 31) == 0) red[t >> 5] = s;
    __syncthreads();
    if (t == 0) {
        float ss = 0.f;
#pragma unroll
        for (int w = 0; w < 8; w++) ss += red[w];
        bval = m + logf(ss);
    }
    __syncthreads();
    float lse = bval;

#pragma unroll
    for (int j = 0; j < 8; j++) {
        int idx = t + j * 256;
        float la = x[j] - lse;
        float a = expf(la);
        lp[idx] = la;
        ap[idx] = a;
        __nv_bfloat16 h = __float2bfloat16(a);
        acp[idx] = h;
        acp[LK + idx] = __float2bfloat16(a - __bfloat162float(h));
    }
}

// ---------------------------------------------------------------------------
extern "C" void kernel_launch(void* const* d_in, const int* in_sizes, int n_in,
                              void* d_out, int out_size) {
    const float* q = (const float*)d_in[0];
    const float* k = (const float*)d_in[1];
    const float* v = (const float*)d_in[2];

    float* out = (float*)d_out;                            // (B, Lq, D)
    float* attn = out + (size_t)BATCH * LQ * DIM;          // (B, Lq, Lk)
    float* logattn = attn + (size_t)BATCH * LQ * LK;       // (B, Lq, Lk)

    // GEMM1: 128x256 tile, 8 warps, 4 stages: smem = 4*(128+256)*64 = 96KB
    constexpr int SM1 = 4 * (128 * 64 + 256 * 64);
    // GEMM2: 128x128 tile, 4 warps, 4 stages: smem = 4*(128+128)*64 = 64KB
    constexpr int SM2 = 4 * (128 * 64 + 128 * 64);

    auto* k1 = gemm_mma_kernel<128, 256, DIM, true, LK, 4>;
    auto* k2 = gemm_mma_kernel<128, 128, LK, false, DIM, 4>;
    cudaFuncSetAttribute(k1, cudaFuncAttributeMaxDynamicSharedMemorySize, SM1);
    cudaFuncSetAttribute(k2, cudaFuncAttributeMaxDynamicSharedMemorySize, SM2);

    // Pass 0: conversions + row sums of squares
    conv_qk_kernel<<<2 * BATCH * LQ, 128>>>(q, k);
    {
        dim3 g(LK / 32, DIM / 32, BATCH);
        conv_v_kernel<<<g, dim3(32, 8)>>>(v);
    }

    // Pass 1: logits (into log_attn region): A=qcat [B*LQ,1280], B=kcat [B*LK,1280]
    {
        __nv_bfloat16* qc; cudaGetSymbolAddress((void**)&qc, g_qcat);
        __nv_bfloat16* kc; cudaGetSymbolAddress((void**)&kc, g_kcat);
        dim3 g(LK / 256, LQ / 128, BATCH);
        k1<<<g, 256, SM1>>>(qc, kc, logattn, LK);
    }

    // Pass 2: softmax (in-place log_attn, attn fp32, attn bf16 hi/lo)
    softmax_kernel<<<BATCH * LQ, 256>>>(logattn, attn);

    // Pass 3: out = attn @ V: A=acat [B*LQ,4096], B=vt [B*DIM,4096]
    {
        __nv_bfloat16* ac; cudaGetSymbolAddress((void**)&ac, g_acat);
        __nv_bfloat16* vt; cudaGetSymbolAddress((void**)&vt, g_vt);
        dim3 g(DIM / 128, LQ / 128, BATCH);
        k2<<<g, 128, SM2>>>(ac, vt, out, DIM);
    }
}

// round 7
// speedup vs baseline: 1.9960x; 1.0022x over previous
#include <cuda_runtime.h>
#include <cuda_bf16.h>
#include <math.h>
#include <stdint.h>

#define BATCH 8
#define LQ 2048
#define LK 2048
#define DIM 640
#define INV_TEMP (1.0f / 13.0f)

// ---------------------------------------------------------------------------
// Device scratch (allocation-free rule: __device__ globals)
// split-bf16 concatenated operands: row-major, K' = 2*K (first K = hi, next K = lo)
// ---------------------------------------------------------------------------
__device__ float g_qq[BATCH * LQ];
__device__ float g_kk[BATCH * LK];
__device__ __nv_bfloat16 g_qcat[(size_t)BATCH * LQ * 2 * DIM];   // [B*LQ, 1280]
__device__ __nv_bfloat16 g_kcat[(size_t)BATCH * LK * 2 * DIM];   // [B*LK, 1280]
__device__ __nv_bfloat16 g_vt[(size_t)BATCH * DIM * 2 * LK];     // [B*DIM, 4096] (v^T)
__device__ __nv_bfloat16 g_acat[(size_t)BATCH * LQ * 2 * LK];    // [B*LQ, 4096]

// ---------------------------------------------------------------------------
// helpers
// ---------------------------------------------------------------------------
__device__ __forceinline__ uint32_t smem_u32(const void* p) {
    uint32_t a;
    asm("{ .reg .u64 t; cvta.to.shared.u64 t, %1; cvt.u32.u64 %0, t; }" : "=r"(a) : "l"(p));
    return a;
}
__device__ __forceinline__ void cp16(uint32_t dst, const void* src) {
    asm volatile("cp.async.cg.shared.global [%0], [%1], 16;" :: "r"(dst), "l"(src) : "memory");
}
__device__ __forceinline__ void ldmx4(uint32_t* r, uint32_t addr) {
    asm volatile("ldmatrix.sync.aligned.m8n8.x4.shared.b16 {%0,%1,%2,%3}, [%4];"
                 : "=r"(r[0]), "=r"(r[1]), "=r"(r[2]), "=r"(r[3]) : "r"(addr));
}
__device__ __forceinline__ void mma16816(float* c, const uint32_t* a, uint32_t b0, uint32_t b1) {
    asm volatile(
        "mma.sync.aligned.m16n8k16.row.col.f32.bf16.bf16.f32 "
        "{%0,%1,%2,%3}, {%4,%5,%6,%7}, {%8,%9}, {%0,%1,%2,%3};"
        : "+f"(c[0]), "+f"(c[1]), "+f"(c[2]), "+f"(c[3])
        : "r"(a[0]), "r"(a[1]), "r"(a[2]), "r"(a[3]), "r"(b0), "r"(b1));
}

// ---------------------------------------------------------------------------
// Pass 0a: q,k -> hi/lo bf16 concatenated arrays + row sum-of-squares
// ---------------------------------------------------------------------------
__global__ __launch_bounds__(128)
void conv_qk_kernel(const float* __restrict__ q, const float* __restrict__ k) {
    int row = blockIdx.x;
    bool isQ = row < BATCH * LQ;
    int r = isQ ? row : row - BATCH * LQ;
    const float* src = (isQ ? q : k) + (size_t)r * DIM;
    __nv_bfloat16* dst = (isQ ? g_qcat : g_kcat) + (size_t)r * 2 * DIM;

    float s = 0.f;
    for (int i = threadIdx.x; i < DIM; i += 128) {
        float x = src[i];
        s = fmaf(x, x, s);
        __nv_bfloat16 h = __float2bfloat16(x);
        dst[i] = h;
        dst[DIM + i] = __float2bfloat16(x - __bfloat162float(h));
    }
#pragma unroll
    for (int off = 16; off > 0; off >>= 1)
        s += __shfl_down_sync(0xffffffffu, s, off);
    __shared__ float ws[4];
    if ((threadIdx.x & 31) == 0) ws[threadIdx.x >> 5] = s;
    __syncthreads();
    if (threadIdx.x == 0) {
        float t = ws[0] + ws[1] + ws[2] + ws[3];
        if (isQ) g_qq[r] = t; else g_kk[r] = t;
    }
}

// ---------------------------------------------------------------------------
// Pass 0b: v -> transposed hi/lo bf16: g_vt[(b*DIM+d), k](hi), [.., LK+k](lo)
// ---------------------------------------------------------------------------
__global__ __launch_bounds__(256)
void conv_v_kernel(const float* __restrict__ v) {
    __shared__ float tile[32][33];
    int b = blockIdx.z;
    int k0 = blockIdx.x * 32;
    int d0 = blockIdx.y * 32;
    int tx = threadIdx.x, ty = threadIdx.y;
#pragma unroll
    for (int i = ty; i < 32; i += 8)
        tile[i][tx] = v[((size_t)b * LK + k0 + i) * DIM + d0 + tx];
    __syncthreads();
#pragma unroll
    for (int i = ty; i < 32; i += 8) {
        float x = tile[tx][i];  // v[k0+tx][d0+i]
        __nv_bfloat16 h = __float2bfloat16(x);
        __nv_bfloat16 l = __float2bfloat16(x - __bfloat162float(h));
        size_t rowbase = ((size_t)b * DIM + d0 + i) * (2 * LK);
        g_vt[rowbase + k0 + tx] = h;
        g_vt[rowbase + LK + k0 + tx] = l;
    }
}

// ---------------------------------------------------------------------------
// mma.sync split-bf16 GEMM. CTA tile MT x NT, warps of 64x64 in (MT/64, NT/64).
// A rows: [hi(0:HALFK) | lo(HALFK:2*HALFK)], same for B; 3 passes hh, lh, hl.
// NSTAGE-deep cp.async pipeline, 32-wide k chunks.
// LOGITS: C = (2*acc - qq[m] - kk[n]) / 13.
// ---------------------------------------------------------------------------
template <int MT, int NT, int HALFK, bool LOGITS, int BROWS, int NSTAGE>
__global__ __launch_bounds__((MT / 64) * (NT / 64) * 32, 256 / ((MT / 64) * (NT / 64) * 32))
void gemm_mma_kernel(const __nv_bfloat16* __restrict__ Ag,
                     const __nv_bfloat16* __restrict__ Bg,
                     float* __restrict__ C, int ldc) {
    constexpr int WM = MT / 64;
    constexpr int WN = NT / 64;
    constexpr int NTHR = WM * WN * 32;
    constexpr int STRIDE = 2 * HALFK;
    constexpr int KCH = HALFK / 32;     // 32-wide k chunks per pass
    constexpr int NCH = 3 * KCH;
    constexpr int ABYTES = MT * 64;     // MT rows x 32 bf16
    constexpr int BBYTES = NT * 64;

    extern __shared__ char dsm[];
    const uint32_t uA = smem_u32(dsm);
    const uint32_t uB = uA + NSTAGE * ABYTES;

    int t = threadIdx.x;
    int wid = t >> 5, lane = t & 31;
    int warp_m = wid % WM;
    int warp_n = wid / WM;
    int b = blockIdx.z;
    int m0 = blockIdx.y * MT;
    int n0 = blockIdx.x * NT;
    size_t arow0 = (size_t)b * LQ + m0;
    size_t brow0 = (size_t)b * BROWS + n0;

    auto load_chunk = [&](int ck, int st) {
        int pass = ck / KCH;
        int kc = (ck - pass * KCH) * 32;
        int aoff = (pass == 1) ? HALFK : 0;
        int boff = (pass == 2) ? HALFK : 0;
        const __nv_bfloat16* ab = Ag + arow0 * STRIDE + aoff + kc;
        const __nv_bfloat16* bb = Bg + brow0 * STRIDE + boff + kc;
#pragma unroll
        for (int p = t; p < MT * 4; p += NTHR) {
            int row = p >> 2, c = p & 3;
            int cs = c ^ ((row >> 1) & 3);
            cp16(uA + st * ABYTES + row * 64 + cs * 16, ab + (size_t)row * STRIDE + c * 8);
        }
#pragma unroll
        for (int p = t; p < NT * 4; p += NTHR) {
            int row = p >> 2, c = p & 3;
            int cs = c ^ ((row >> 1) & 3);
            cp16(uB + st * BBYTES + row * 64 + cs * 16, bb + (size_t)row * STRIDE + c * 8);
        }
    };

    float acc[4][8][4];
#pragma unroll
    for (int i = 0; i < 4; i++)
#pragma unroll
        for (int j = 0; j < 8; j++)
#pragma unroll
            for (int u = 0; u < 4; u++) acc[i][j][u] = 0.f;

    // prologue
#pragma unroll
    for (int s = 0; s < NSTAGE - 1; s++) {
        if (s < NCH) load_chunk(s, s);
        asm volatile("cp.async.commit_group;" ::: "memory");
    }

    int lr16 = lane & 15;          // row within 16-row tile
    int hi16 = lane >> 4;          // 16B chunk selector within k16

    for (int s = 0; s < NCH; s++) {
        int pf = s + NSTAGE - 1;
        if (pf < NCH) load_chunk(pf, pf % NSTAGE);
        asm volatile("cp.async.commit_group;" ::: "memory");
        asm volatile("cp.async.wait_group %0;" :: "n"(NSTAGE - 1) : "memory");
        __syncthreads();

        int st = s % NSTAGE;
        uint32_t aBase = uA + st * ABYTES;
        uint32_t bBase = uB + st * BBYTES;
#pragma unroll
        for (int ks = 0; ks < 2; ks++) {
            int c = ks * 2 + hi16;
            uint32_t afr[4][4];
#pragma unroll
            for (int mt = 0; mt < 4; mt++) {
                int row = warp_m * 64 + mt * 16 + lr16;
                int cs = c ^ ((row >> 1) & 3);
                ldmx4(afr[mt], aBase + row * 64 + cs * 16);
            }
            uint32_t bfr[4][4];
#pragma unroll
            for (int np = 0; np < 4; np++) {
                int row = warp_n * 64 + np * 16 + lr16;
                int cs = c ^ ((row >> 1) & 3);
                ldmx4(bfr[np], bBase + row * 64 + cs * 16);
            }
#pragma unroll
            for (int mt = 0; mt < 4; mt++)
#pragma unroll
                for (int nt = 0; nt < 8; nt++) {
                    int np = nt >> 1, sel = nt & 1;
                    mma16816(acc[mt][nt], afr[mt], bfr[np][sel], bfr[np][sel + 2]);
                }
        }
        __syncthreads();
    }

    // ---------------- epilogue ----------------
    int lr = lane >> 2;            // 0..7
    int lc = (lane & 3) * 2;       // 0,2,4,6
#pragma unroll
    for (int mt = 0; mt < 4; mt++) {
#pragma unroll
        for (int h = 0; h < 2; h++) {
            int row = m0 + warp_m * 64 + mt * 16 + h * 8 + lr;
            size_t crow = (size_t)b * LQ + row;
            float qqv = LOGITS ? g_qq[crow] : 0.f;
            float* cp = C + crow * ldc + n0 + warp_n * 64 + lc;
#pragma unroll
            for (int nt = 0; nt < 8; nt++) {
                float v0 = acc[mt][nt][h * 2 + 0];
                float v1 = acc[mt][nt][h * 2 + 1];
                if (LOGITS) {
                    int col = b * LK + n0 + warp_n * 64 + nt * 8 + lc;
                    v0 = (2.f * v0 - qqv - g_kk[col]) * INV_TEMP;
                    v1 = (2.f * v1 - qqv - g_kk[col + 1]) * INV_TEMP;
                }
                float2 w; w.x = v0; w.y = v1;
                *(float2*)(cp + nt * 8) = w;
            }
        }
    }
}

// ---------------------------------------------------------------------------
// Pass 3: row softmax; rewrites log_attn in place, writes attn fp32 and
// attn hi/lo bf16 (g_acat) for the AV GEMM.
// ---------------------------------------------------------------------------
__global__ __launch_bounds__(256)
void softmax_kernel(float* __restrict__ logattn, float* __restrict__ attn) {
    size_t row = blockIdx.x;
    float* lp = logattn + row * LK;
    float* ap = attn + row * LK;
    __nv_bfloat16* acp = g_acat + row * (size_t)(2 * LK);
    int t = threadIdx.x;

    float x[8];
#pragma unroll
    for (int j = 0; j < 8; j++) x[j] = lp[t + j * 256];

    float m = x[0];
#pragma unroll
    for (int j = 1; j < 8; j++) m = fmaxf(m, x[j]);
#pragma unroll
    for (int off = 16; off > 0; off >>= 1)
        m = fmaxf(m, __shfl_xor_sync(0xffffffffu, m, off));
    __shared__ float red[8];
    __shared__ float bval;
    if ((t & 31) == 0) red[t >> 5] = m;
    __syncthreads();
    if (t == 0) {
        float mm = red[0];
#pragma unroll
        for (int w = 1; w < 8; w++) mm = fmaxf(mm, red[w]);
        bval = mm;
    }
    __syncthreads();
    m = bval;

    float s = 0.f;
#pragma unroll
    for (int j = 0; j < 8; j++) s += expf(x[j] - m);
#pragma unroll
    for (int off = 16; off > 0; off >>= 1)
        s += __shfl_xor_sync(0xffffffffu, s, off);
    __syncthreads();
    if ((t & 31) == 0) red[t >> 5] = s;
    __syncthreads();
    if (t == 0) {
        float ss = 0.f;
#pragma unroll
        for (int w = 0; w < 8; w++) ss += red[w];
        bval = m + logf(ss);
    }
    __syncthreads();
    float lse = bval;

#pragma unroll
    for (int j = 0; j < 8; j++) {
        int idx = t + j * 256;
        float la = x[j] - lse;
        float a = expf(la);
        lp[idx] = la;
        ap[idx] = a;
        __nv_bfloat16 h = __float2bfloat16(a);
        acp[idx] = h;
        acp[LK + idx] = __float2bfloat16(a - __bfloat162float(h));
    }
}

// ---------------------------------------------------------------------------
extern "C" void kernel_launch(void* const* d_in, const int* in_sizes, int n_in,
                              void* d_out, int out_size) {
    const float* q = (const float*)d_in[0];
    const float* k = (const float*)d_in[1];
    const float* v = (const float*)d_in[2];

    float* out = (float*)d_out;                            // (B, Lq, D)
    float* attn = out + (size_t)BATCH * LQ * DIM;          // (B, Lq, Lk)
    float* logattn = attn + (size_t)BATCH * LQ * LK;       // (B, Lq, Lk)

    // GEMM1: 128x256 tile, 8 warps, 4 stages: smem = 4*(128+256)*64 = 96KB
    constexpr int SM1 = 4 * (128 * 64 + 256 * 64);
    // GEMM2: 128x128 tile, 4 warps, 4 stages: smem = 4*(128+128)*64 = 64KB
    constexpr int SM2 = 4 * (128 * 64 + 128 * 64);

    auto* k1 = gemm_mma_kernel<128, 256, DIM, true, LK, 4>;
    auto* k2 = gemm_mma_kernel<128, 128, LK, false, DIM, 4>;
    cudaFuncSetAttribute(k1, cudaFuncAttributeMaxDynamicSharedMemorySize, SM1);
    cudaFuncSetAttribute(k2, cudaFuncAttributeMaxDynamicSharedMemorySize, SM2);

    // Pass 0: conversions + row sums of squares
    conv_qk_kernel<<<2 * BATCH * LQ, 128>>>(q, k);
    {
        dim3 g(LK / 32, DIM / 32, BATCH);
        conv_v_kernel<<<g, dim3(32, 8)>>>(v);
    }

    // Pass 1: logits (into log_attn region): A=qcat [B*LQ,1280], B=kcat [B*LK,1280]
    {
        __nv_bfloat16* qc; cudaGetSymbolAddress((void**)&qc, g_qcat);
        __nv_bfloat16* kc; cudaGetSymbolAddress((void**)&kc, g_kcat);
        dim3 g(LK / 256, LQ / 128, BATCH);
        k1<<<g, 256, SM1>>>(qc, kc, logattn, LK);
    }

    // Pass 2: softmax (in-place log_attn, attn fp32, attn bf16 hi/lo)
    softmax_kernel<<<BATCH * LQ, 256>>>(logattn, attn);

    // Pass 3: out = attn @ V: A=acat [B*LQ,4096], B=vt [B*DIM,4096]
    {
        __nv_bfloat16* ac; cudaGetSymbolAddress((void**)&ac, g_acat);
        __nv_bfloat16* vt; cudaGetSymbolAddress((void**)&vt, g_vt);
        dim3 g(DIM / 128, LQ / 128, BATCH);
        k2<<<g, 128, SM2>>>(ac, vt, out, DIM);
    }
}